// round 6
// baseline (speedup 1.0000x reference)
#include <cuda_runtime.h>
#include <math.h>

// Elman RNN, fp32. B=128, S=1024, I=256, H=512, O=256, N_TARGETS=1.
// Phase A: P[t][j][b] (fma2-packed GEMM)
// Phase B: persistent, 128 CTAs = 8 j-tiles(64) x 16 CTA-pairs.
//          Two independent batch chains per CTA, PROPERLY skewed:
//          wait/stage of each chain sits right before its own compute, so
//          each chain's h-exchange hides behind the other chain's compute.
// Phase C: output = h_T @ W_h2o^T + b_h2o ; hidden appended if requested.

typedef unsigned long long ull;

namespace {
constexpr int S = 1024, B = 128, I = 256, H = 512, O = 256;
constexpr int NJ = 8;                 // arrivals per group per step
constexpr int JT = 64;                // j per CTA
constexpr int BG = 4;                 // b per chain-group
constexpr int NBG = B / BG;           // 32 groups
constexpr int GSZ = H * BG;           // 2048 floats per group h slab [b][k]
constexpr int HSTR = 520;             // padded h_s row stride ([b][k])
constexpr int PPAD = 72;              // p_s b-row stride
constexpr int PKZ = BG * PPAD;        // 288 floats per kz plane
constexpr int W_S = H * JT;           // 32768
constexpr int H_S = BG * HSTR;        // 2080 per chain
constexpr int SMEM_B_FLOATS = W_S + 2 * H_S + 8 * PKZ;
constexpr int SMEM_B_BYTES = SMEM_B_FLOATS * 4;   // ~156 KB
}

__device__ float g_P[(size_t)S * H * B];     // [t][j][b] pre-activations
__device__ float g_H[2][NBG * GSZ];          // ping-pong h: [par][grp][b][k]
__device__ struct { unsigned v; unsigned pad[31]; } g_bar[NBG];

__device__ __forceinline__ ull pack2(float x) {
    ull r;
    asm("mov.b64 %0, {%1, %1};" : "=l"(r) : "f"(x));
    return r;
}
__device__ __forceinline__ float2 unpack2(ull v) {
    float2 r;
    asm("mov.b64 {%0, %1}, %2;" : "=f"(r.x), "=f"(r.y) : "l"(v));
    return r;
}
__device__ __forceinline__ void fma2(ull& d, ull a, ull b) {
    asm("fma.rn.f32x2 %0, %1, %2, %0;" : "+l"(d) : "l"(a), "l"(b));
}
__device__ __forceinline__ void spin_ctr(unsigned* ctr, unsigned target) {
    unsigned v;
    do {
        asm volatile("ld.acquire.gpu.u32 %0, [%1];"
                     : "=r"(v) : "l"(ctr) : "memory");
    } while (v < target);
}
__device__ __forceinline__ void arrive_ctr(unsigned* ctr) {
    asm volatile("red.release.gpu.global.add.u32 [%0], 1;" :: "l"(ctr) : "memory");
}

// ---------------- Phase A: pre-activation GEMM (fma2-packed) ----------------
__global__ void __launch_bounds__(256) phaseA_kernel(
    const float* __restrict__ seq, const float* __restrict__ Wi2h,
    const float* __restrict__ bi2h) {
    const int t = blockIdx.x;
    const int j0 = blockIdx.y * 128;
    const int tid = threadIdx.x;
    const int tx = tid & 15;   // 8 b per thread
    const int ty = tid >> 4;   // 8 j per thread (4 fma2 pairs)
    __shared__ float sh_a[16 * 132];  // [k][j], padded
    __shared__ float sh_b[16 * 132];  // [k][b], padded
    ull acc[4][8];
#pragma unroll
    for (int r = 0; r < 4; r++)
#pragma unroll
        for (int c = 0; c < 8; c++) acc[r][c] = 0;

    for (int k0 = 0; k0 < I; k0 += 16) {
        __syncthreads();
#pragma unroll
        for (int q = 0; q < 2; q++) {
            int idx = tid + q * 256;  // 0..511
            int j = idx >> 2, kq = idx & 3;
            float4 v = *(const float4*)(Wi2h + (size_t)(j0 + j) * (I + H) + k0 + kq * 4);
            sh_a[(kq * 4 + 0) * 132 + j] = v.x;
            sh_a[(kq * 4 + 1) * 132 + j] = v.y;
            sh_a[(kq * 4 + 2) * 132 + j] = v.z;
            sh_a[(kq * 4 + 3) * 132 + j] = v.w;
        }
#pragma unroll
        for (int q = 0; q < 2; q++) {
            int idx = tid + q * 256;
            int b = idx >> 2, kq = idx & 3;
            float4 v = *(const float4*)(seq + (size_t)b * (S * I) + (size_t)t * I + k0 + kq * 4);
            sh_b[(kq * 4 + 0) * 132 + b] = v.x;
            sh_b[(kq * 4 + 1) * 132 + b] = v.y;
            sh_b[(kq * 4 + 2) * 132 + b] = v.z;
            sh_b[(kq * 4 + 3) * 132 + b] = v.w;
        }
        __syncthreads();
#pragma unroll
        for (int k = 0; k < 16; k++) {
            ulonglong2 a01 = *(const ulonglong2*)(sh_a + k * 132 + ty * 8);
            ulonglong2 a23 = *(const ulonglong2*)(sh_a + k * 132 + ty * 8 + 4);
            float4 b0 = *(const float4*)(sh_b + k * 132 + tx * 8);
            float4 b1 = *(const float4*)(sh_b + k * 132 + tx * 8 + 4);
            ull bb[8] = {pack2(b0.x), pack2(b0.y), pack2(b0.z), pack2(b0.w),
                         pack2(b1.x), pack2(b1.y), pack2(b1.z), pack2(b1.w)};
#pragma unroll
            for (int c = 0; c < 8; c++) {
                fma2(acc[0][c], a01.x, bb[c]);
                fma2(acc[1][c], a01.y, bb[c]);
                fma2(acc[2][c], a23.x, bb[c]);
                fma2(acc[3][c], a23.y, bb[c]);
            }
        }
    }
#pragma unroll
    for (int r = 0; r < 4; r++) {
        int j = j0 + ty * 8 + r * 2;
        float bj0 = bi2h[j], bj1 = bi2h[j + 1];
        float lo[8], hi[8];
#pragma unroll
        for (int c = 0; c < 8; c++) {
            float2 f = unpack2(acc[r][c]);
            lo[c] = f.x + bj0;
            hi[c] = f.y + bj1;
        }
        float* op0 = g_P + (size_t)t * (H * B) + (size_t)j * B + tx * 8;
        float* op1 = op0 + B;
        *(float4*)op0 = make_float4(lo[0], lo[1], lo[2], lo[3]);
        *(float4*)(op0 + 4) = make_float4(lo[4], lo[5], lo[6], lo[7]);
        *(float4*)op1 = make_float4(hi[0], hi[1], hi[2], hi[3]);
        *(float4*)(op1 + 4) = make_float4(hi[4], hi[5], hi[6], hi[7]);
    }
}

// ---------------- Phase B: persistent recurrence, skewed 2-chain pipeline ---
__global__ void __launch_bounds__(256) phaseB_kernel(const float* __restrict__ Wi2h) {
    extern __shared__ float smem[];
    float* w_s = smem;                    // [512 k][64 j]
    float* h_sA = smem + W_S;             // [4 b][520]
    float* h_sB = h_sA + H_S;
    float* p_s = h_sB + H_S;              // [8 kz][4 b (stride 72)][64 j]

    const int u = blockIdx.x & 15;
    const int jj = blockIdx.x >> 4;
    const int j0 = jj * JT;
    const int gA = u * 2, gB = u * 2 + 1;
    const int tid = threadIdx.x;
    const int kz = tid >> 5;              // warp = k-slice of 64
    const int lane = tid & 31;
    const int ty = lane >> 2;             // j = {ty*4..+3} u {32+ty*4..+3}
    const int tx = lane & 3;              // b within group
    const int bl = tid & 3, jl = tid >> 2;  // reducer mapping

    // Load Wh transposed: w_s[k][j] = Wi2h[(j0+j)*(I+H) + I + k]
#pragma unroll
    for (int q = 0; q < 32; q++) {
        int idx = tid + q * 256;          // 0..8191 float4 slots
        int j = idx >> 7, k4 = idx & 127;
        float4 v = *(const float4*)(Wi2h + (size_t)(j0 + j) * (I + H) + I + k4 * 4);
        w_s[(k4 * 4 + 0) * JT + j] = v.x;
        w_s[(k4 * 4 + 1) * JT + j] = v.y;
        w_s[(k4 * 4 + 2) * JT + j] = v.z;
        w_s[(k4 * 4 + 3) * JT + j] = v.w;
    }

    unsigned* ctrA = &g_bar[gA].v;
    unsigned* ctrB = &g_bar[gB].v;
    const float* wp = w_s + kz * 64 * JT + ty * 4;
    const float* hpA = h_sA + tx * HSTR + kz * 64;
    const float* hpB = h_sB + tx * HSTR + kz * 64;
    float* pst = p_s + kz * PKZ + tx * PPAD + ty * 4;
    const float* prd = p_s + bl * PPAD + jl;

    for (int t = 0; t < S; t++) {
        const float* pPt = g_P + (size_t)t * (H * B) + (size_t)(j0 + jl) * B;
        float pA = pPt[gA * BG + bl];
        float pB = pPt[gB * BG + bl];
        const float* rbase = g_H[t & 1];
        float* wbase = g_H[(t + 1) & 1];

#pragma unroll
        for (int seg = 0; seg < 2; seg++) {
            unsigned* ctr = seg ? ctrB : ctrA;
            const int g = seg ? gB : gA;
            float* h_s = seg ? h_sB : h_sA;
            const float* hp = seg ? hpB : hpA;
            const float pIn = seg ? pB : pA;

            // wait for peers' h(t) of this chain
            // (covered by the other chain's compute segment)
            if (tid == 0) spin_ctr(ctr, (unsigned)t * NJ);
            __syncthreads();
            // stage this chain's h slab into [b][520]
            {
                const float4* r4 = (const float4*)(rbase + g * GSZ);
#pragma unroll
                for (int q = 0; q < 2; q++) {
                    int idx = tid + q * 256;     // 0..511
                    int b = idx >> 7, k4 = idx & 127;
                    *(float4*)(h_s + b * HSTR + k4 * 4) = r4[idx];
                }
            }
            __syncthreads();

            // compute: 8 j x 1 b per thread, fma2 over j-pairs
            ull a0 = 0, a1 = 0, a2 = 0, a3 = 0;
#pragma unroll 4
            for (int k4 = 0; k4 < 16; k4++) {
                float4 h4 = *(const float4*)(hp + k4 * 4);
                ull hh[4] = {pack2(h4.x), pack2(h4.y), pack2(h4.z), pack2(h4.w)};
#pragma unroll
                for (int i = 0; i < 4; i++) {
                    const float* wr = wp + (k4 * 4 + i) * JT;
                    ulonglong2 wA = *(const ulonglong2*)wr;
                    ulonglong2 wB = *(const ulonglong2*)(wr + 32);
                    fma2(a0, wA.x, hh[i]);
                    fma2(a1, wA.y, hh[i]);
                    fma2(a2, wB.x, hh[i]);
                    fma2(a3, wB.y, hh[i]);
                }
            }
            *(ull*)(pst + 0) = a0;
            *(ull*)(pst + 2) = a1;
            *(ull*)(pst + 32) = a2;
            *(ull*)(pst + 34) = a3;
            __syncthreads();

            // reduce 8 kz partials + P, tanh, write h(t+1)
            {
                float s = pIn;
#pragma unroll
                for (int z = 0; z < 8; z++) s += prd[z * PKZ];
                wbase[g * GSZ + bl * H + j0 + jl] = tanhf(s);
            }
            __syncthreads();
            if (tid == 0) arrive_ctr(ctr);
        }
    }
}

// ---------------- Phase C: output projection + hidden emit ----------------
__global__ void __launch_bounds__(256) phaseC_kernel(
    const float* __restrict__ Wh2o, const float* __restrict__ bh2o,
    float* __restrict__ out, int out_size) {
    const float* hfin = g_H[S & 1];            // parity 0 after 1024 steps
    int idx = blockIdx.x * 256 + threadIdx.x;  // 0..32767
    int o = idx >> 7, b = idx & 127;
    const float4* hrow = (const float4*)(hfin + (b >> 2) * GSZ + (b & 3) * H);
    const float4* wrow = (const float4*)(Wh2o + (size_t)o * H);
    float4 c = {0.f, 0.f, 0.f, 0.f};
#pragma unroll 8
    for (int q = 0; q < H / 4; q++) {
        float4 w = wrow[q];
        float4 h = hrow[q];
        c.x = fmaf(w.x, h.x, c.x);
        c.y = fmaf(w.y, h.y, c.y);
        c.z = fmaf(w.z, h.z, c.z);
        c.w = fmaf(w.w, h.w, c.w);
    }
    float acc = bh2o[o] + (c.x + c.y) + (c.z + c.w);
    int oidx = b * O + o;                      // output (B,1,O)
    if (oidx < out_size) out[oidx] = acc;
    if (out_size >= B * O + B * H) {
#pragma unroll
        for (int q = 0; q < 2; q++) {
            int e = idx + q * (B * O);         // 0..65535
            int hb = e >> 9, hk = e & 511;
            out[B * O + e] = hfin[(hb >> 2) * GSZ + (hb & 3) * H + hk];
        }
    }
}

extern "C" void kernel_launch(void* const* d_in, const int* in_sizes, int n_in,
                              void* d_out, int out_size) {
    const float* seq  = (const float*)d_in[0];
    const float* Wi2h = (const float*)d_in[1];
    const float* bi2h = (const float*)d_in[2];
    const float* Wh2o = (const float*)d_in[3];
    const float* bh2o = (const float*)d_in[4];
    float* out = (float*)d_out;

    cudaFuncSetAttribute(phaseB_kernel,
                         cudaFuncAttributeMaxDynamicSharedMemorySize, SMEM_B_BYTES);

    void* pBar = nullptr;
    cudaGetSymbolAddress(&pBar, g_bar);
    cudaMemsetAsync(pBar, 0, sizeof(g_bar), 0);
    void* pH = nullptr;
    cudaGetSymbolAddress(&pH, g_H);
    cudaMemsetAsync(pH, 0, (size_t)NBG * GSZ * sizeof(float), 0);  // h(0) = 0

    phaseA_kernel<<<dim3(S, H / 128), 256>>>(seq, Wi2h, bi2h);
    phaseB_kernel<<<128, 256, SMEM_B_BYTES>>>(Wi2h);
    phaseC_kernel<<<(B * O) / 256, 256>>>(Wh2o, bh2o, out, out_size);
}

// round 7
// speedup vs baseline: 1.0558x; 1.0558x over previous
#include <cuda_runtime.h>
#include <math.h>

// Elman RNN, fp32. B=128, S=1024, I=256, H=512, O=256, N_TARGETS=1.
// Phase A: P[t][b][j] = x_t @ Wx^T + bias        (fma2-packed GEMM)
// Phase B: persistent, 128 CTAs = 8 j-tiles(64j) x 16 b-groups(8b).
//          Slice-pipelined consumption of h(t): own 64-k slice first (no
//          wait), remaining 7 slices LDG-prefetched while computing.
//          Register accumulators across slices; one 16-way k-split reduce,
//          tanh, publish; one 8-arrival counter per group per step.
// Phase C: output = h @ W_h2o^T + b_h2o ; hidden appended if requested.

typedef unsigned long long ull;

namespace {
constexpr int S = 1024, B = 128, I = 256, H = 512, O = 256;
constexpr int NJ = 8;                 // CTAs (j-tiles) per b-group
constexpr int JT = 64;                // j per CTA
constexpr int BT = 8;                 // b per group
// phase-B smem layout (floats)
constexpr int W_S = H * JT;           // 32768: w_s[k][64j]
constexpr int HROW = 12;              // h_s row stride (48B, conflict-tuned)
constexpr int HSLICE = 64 * HROW;     // 768 per 64-k slice
constexpr int H_S = 8 * HSLICE;       // 6144
constexpr int PROW = 72;              // p_s j-dim stride
constexpr int PPLANE = BT * PROW;     // 576 per ks plane
constexpr int P_S = 16 * PPLANE;      // 9216
constexpr int SMEM_B_BYTES = (W_S + H_S + P_S) * 4;   // 192512 B
}

__device__ float g_P[(size_t)S * B * H];   // [t][b][j] pre-activations
__device__ float g_H[2][B * H];            // ping-pong h: [parity][b][k]
__device__ struct { unsigned v; unsigned pad[31]; } g_bar[B / BT];

__device__ __forceinline__ ull pack2(float x) {
    ull r;
    asm("mov.b64 %0, {%1, %1};" : "=l"(r) : "f"(x));
    return r;
}
__device__ __forceinline__ float2 unpack2(ull v) {
    float2 r;
    asm("mov.b64 {%0, %1}, %2;" : "=f"(r.x), "=f"(r.y) : "l"(v));
    return r;
}
__device__ __forceinline__ void fma2(ull& d, ull a, ull b) {
    asm("fma.rn.f32x2 %0, %1, %2, %0;" : "+l"(d) : "l"(a), "l"(b));
}
__device__ __forceinline__ void spin_ctr(unsigned* ctr, unsigned target) {
    unsigned v;
    do {
        asm volatile("ld.acquire.gpu.u32 %0, [%1];"
                     : "=r"(v) : "l"(ctr) : "memory");
    } while (v < target);
}
__device__ __forceinline__ void arrive_ctr(unsigned* ctr) {
    asm volatile("red.release.gpu.global.add.u32 [%0], 1;" :: "l"(ctr) : "memory");
}

// ---------------- Phase A: pre-activation GEMM -> P[t][b][j] ----------------
// grid (S, H/128), 256 threads. CTA: 128 b x 128 j for one t, K=I=256.
__global__ void __launch_bounds__(256) phaseA_kernel(
    const float* __restrict__ seq, const float* __restrict__ Wi2h,
    const float* __restrict__ bi2h) {
    const int t = blockIdx.x;
    const int j0 = blockIdx.y * 128;
    const int tid = threadIdx.x;
    const int tx = tid & 15;   // j-block: 8 j per thread
    const int ty = tid >> 4;   // b-block: 8 b per thread (4 fma2 pairs)
    __shared__ float sh_w[16 * 132];  // [k][j], padded
    __shared__ float sh_x[16 * 132];  // [k][b], padded
    ull acc[4][8];                    // [b-pair][j]
#pragma unroll
    for (int r = 0; r < 4; r++)
#pragma unroll
        for (int c = 0; c < 8; c++) acc[r][c] = 0;

    for (int k0 = 0; k0 < I; k0 += 16) {
        __syncthreads();
#pragma unroll
        for (int q = 0; q < 2; q++) {
            int idx = tid + q * 256;  // 0..511
            int j = idx >> 2, kq = idx & 3;
            float4 v = *(const float4*)(Wi2h + (size_t)(j0 + j) * (I + H) + k0 + kq * 4);
            sh_w[(kq * 4 + 0) * 132 + j] = v.x;
            sh_w[(kq * 4 + 1) * 132 + j] = v.y;
            sh_w[(kq * 4 + 2) * 132 + j] = v.z;
            sh_w[(kq * 4 + 3) * 132 + j] = v.w;
        }
#pragma unroll
        for (int q = 0; q < 2; q++) {
            int idx = tid + q * 256;
            int b = idx >> 2, kq = idx & 3;
            float4 v = *(const float4*)(seq + (size_t)b * (S * I) + (size_t)t * I + k0 + kq * 4);
            sh_x[(kq * 4 + 0) * 132 + b] = v.x;
            sh_x[(kq * 4 + 1) * 132 + b] = v.y;
            sh_x[(kq * 4 + 2) * 132 + b] = v.z;
            sh_x[(kq * 4 + 3) * 132 + b] = v.w;
        }
        __syncthreads();
#pragma unroll
        for (int k = 0; k < 16; k++) {
            ulonglong2 x01 = *(const ulonglong2*)(sh_x + k * 132 + ty * 8);
            ulonglong2 x23 = *(const ulonglong2*)(sh_x + k * 132 + ty * 8 + 4);
            float4 w0 = *(const float4*)(sh_w + k * 132 + tx * 8);
            float4 w1 = *(const float4*)(sh_w + k * 132 + tx * 8 + 4);
            ull ww[8] = {pack2(w0.x), pack2(w0.y), pack2(w0.z), pack2(w0.w),
                         pack2(w1.x), pack2(w1.y), pack2(w1.z), pack2(w1.w)};
#pragma unroll
            for (int c = 0; c < 8; c++) {
                fma2(acc[0][c], x01.x, ww[c]);
                fma2(acc[1][c], x01.y, ww[c]);
                fma2(acc[2][c], x23.x, ww[c]);
                fma2(acc[3][c], x23.y, ww[c]);
            }
        }
    }
    // epilogue: bias per j, write P[t][b][j] (coalesced along j)
    float4 bj0 = *(const float4*)(bi2h + j0 + tx * 8);
    float4 bj1 = *(const float4*)(bi2h + j0 + tx * 8 + 4);
    float bj[8] = {bj0.x, bj0.y, bj0.z, bj0.w, bj1.x, bj1.y, bj1.z, bj1.w};
#pragma unroll
    for (int r = 0; r < 4; r++) {
        float lo[8], hi[8];
#pragma unroll
        for (int c = 0; c < 8; c++) {
            float2 f = unpack2(acc[r][c]);
            lo[c] = f.x + bj[c];
            hi[c] = f.y + bj[c];
        }
        int b_even = ty * 8 + 2 * r;
        float* op0 = g_P + (size_t)t * (B * H) + (size_t)b_even * H + j0 + tx * 8;
        float* op1 = op0 + H;
        *(float4*)op0 = make_float4(lo[0], lo[1], lo[2], lo[3]);
        *(float4*)(op0 + 4) = make_float4(lo[4], lo[5], lo[6], lo[7]);
        *(float4*)op1 = make_float4(hi[0], hi[1], hi[2], hi[3]);
        *(float4*)(op1 + 4) = make_float4(hi[4], hi[5], hi[6], hi[7]);
    }
}

// ---------------- Phase B: slice-pipelined persistent recurrence ------------
__global__ void __launch_bounds__(256) phaseB_kernel(const float* __restrict__ Wi2h) {
    extern __shared__ float smem[];
    float* w_s = smem;                 // [512 k][64 j]
    float* h_s = smem + W_S;           // [8 slice][64 k (stride 12)][8 b]
    float* p_s = h_s + H_S;            // [16 ks][8 b (stride 72)][64 j]

    const int g = blockIdx.x & 15;     // b-group
    const int jj = blockIdx.x >> 4;    // j-tile = own slice id
    const int j0 = jj * JT;
    const int tid = threadIdx.x;
    const int lane = tid & 31;
    const int warp = tid >> 5;
    const int jg = lane & 7;           // 8 j per thread at jg*8
    const int bg = (lane >> 3) & 1;    // 4 b per thread at bg*4
    const int kb = lane >> 4;
    const int ks = warp * 2 + kb;      // 16-way within-slice k split (4 k each)

    // Load Wh transposed: w_s[k][j] = Wi2h[(j0+j)*(I+H) + I + k]
#pragma unroll
    for (int q = 0; q < 32; q++) {
        int idx = tid + q * 256;       // 0..8191 float4 slots
        int j = idx >> 7, k4 = idx & 127;
        float4 v = *(const float4*)(Wi2h + (size_t)(j0 + j) * (I + H) + I + k4 * 4);
        w_s[(k4 * 4 + 0) * JT + j] = v.x;
        w_s[(k4 * 4 + 1) * JT + j] = v.y;
        w_s[(k4 * 4 + 2) * JT + j] = v.z;
        w_s[(k4 * 4 + 3) * JT + j] = v.w;
    }
    for (int q = tid; q < H_S; q += 256) h_s[q] = 0.f;   // h(0) = 0
    __syncthreads();

    unsigned* ctr = &g_bar[g].v;
    const int rj = tid & 63;           // reducer: j local
    const int rb = (tid >> 6) * 2;     // reducer: b pair base
    const int lb = tid >> 4;           // loader (tid<128): b 0..7
    const int lk4 = tid & 15;          // loader: k4 0..15

    ull acc[4][4];                     // [j-pair][b]

    auto compute_slice = [&](int z) {
        const float* wrow = w_s + (z * 64 + ks * 4) * JT + jg * 8;
        const float* hrow = h_s + z * HSLICE + (ks * 4) * HROW + bg * 4;
#pragma unroll
        for (int ii = 0; ii < 4; ii++) {
            ulonglong2 wA = *(const ulonglong2*)(wrow + ii * JT);
            ulonglong2 wB = *(const ulonglong2*)(wrow + ii * JT + 4);
            float4 hv = *(const float4*)(hrow + ii * HROW);
            ull h0 = pack2(hv.x), h1 = pack2(hv.y), h2 = pack2(hv.z), h3 = pack2(hv.w);
            fma2(acc[0][0], wA.x, h0); fma2(acc[0][1], wA.x, h1);
            fma2(acc[0][2], wA.x, h2); fma2(acc[0][3], wA.x, h3);
            fma2(acc[1][0], wA.y, h0); fma2(acc[1][1], wA.y, h1);
            fma2(acc[1][2], wA.y, h2); fma2(acc[1][3], wA.y, h3);
            fma2(acc[2][0], wB.x, h0); fma2(acc[2][1], wB.x, h1);
            fma2(acc[2][2], wB.x, h2); fma2(acc[2][3], wB.x, h3);
            fma2(acc[3][0], wB.y, h0); fma2(acc[3][1], wB.y, h1);
            fma2(acc[3][2], wB.y, h2); fma2(acc[3][3], wB.y, h3);
        }
    };

    for (int t = 0; t < S; t++) {
        // wait for all peers' h(t) publishes
        if (tid == 0) spin_ctr(ctr, (unsigned)t * NJ);
        __syncthreads();

        const float* rglob = g_H[t & 1] + (size_t)(g * BT) * H;  // [8b][512k]
        float* wglob = g_H[(t + 1) & 1] + (size_t)(g * BT) * H;

        // P prefetch (consumed in reduce, ~2.5K cyc later)
        const float* pP = g_P + (size_t)t * (B * H) + (size_t)(g * BT) * H;
        float pv0 = pP[(rb + 0) * H + j0 + rj];
        float pv1 = pP[(rb + 1) * H + j0 + rj];

        // prefetch remote slice i=1
        float4 pre = make_float4(0.f, 0.f, 0.f, 0.f);
        if (tid < 128) {
            int z1 = (jj + 1) & 7;
            pre = *(const float4*)(rglob + lb * H + z1 * 64 + lk4 * 4);
        }

#pragma unroll
        for (int jp = 0; jp < 4; jp++)
#pragma unroll
            for (int bi = 0; bi < 4; bi++) acc[jp][bi] = 0;

        // own slice first: no exchange needed (written locally last step)
        compute_slice(jj);

#pragma unroll
        for (int i = 1; i < 8; i++) {
            int z = (jj + i) & 7;
            if (tid < 128) {
                float* hd = h_s + z * HSLICE + (lk4 * 4) * HROW + lb;
                hd[0 * HROW] = pre.x;
                hd[1 * HROW] = pre.y;
                hd[2 * HROW] = pre.z;
                hd[3 * HROW] = pre.w;
                if (i < 7) {
                    int zn = (jj + i + 1) & 7;
                    pre = *(const float4*)(rglob + lb * H + zn * 64 + lk4 * 4);
                }
            }
            __syncthreads();
            compute_slice(z);
        }

        // store k-split partials
        {
            float* pst = p_s + ks * PPLANE + (bg * 4) * PROW + jg * 8;
#pragma unroll
            for (int bi = 0; bi < 4; bi++) {
#pragma unroll
                for (int jp = 0; jp < 4; jp++)
                    *(ull*)(pst + bi * PROW + 2 * jp) = acc[jp][bi];
            }
        }
        __syncthreads();

        // reduce 16 partials + P, tanh, publish + keep own slice local
        {
            float s0 = pv0, s1 = pv1;
            const float* prd = p_s + rb * PROW + rj;
#pragma unroll
            for (int z = 0; z < 16; z++) {
                s0 += prd[z * PPLANE];
                s1 += prd[z * PPLANE + PROW];
            }
            float h0 = tanhf(s0), h1 = tanhf(s1);
            wglob[(rb + 0) * H + j0 + rj] = h0;
            wglob[(rb + 1) * H + j0 + rj] = h1;
            float* od = h_s + jj * HSLICE + rj * HROW + rb;
            od[0] = h0;
            od[1] = h1;
        }
        __syncthreads();
        if (tid == 0) arrive_ctr(ctr);
    }
}

// ---------------- Phase C: output projection + hidden emit ----------------
__global__ void __launch_bounds__(256) phaseC_kernel(
    const float* __restrict__ Wh2o, const float* __restrict__ bh2o,
    float* __restrict__ out, int out_size) {
    const float* hfin = g_H[S & 1];            // written at final step
    int idx = blockIdx.x * 256 + threadIdx.x;  // 0..32767
    int o = idx >> 7, b = idx & 127;
    const float4* hrow = (const float4*)(hfin + (size_t)b * H);
    const float4* wrow = (const float4*)(Wh2o + (size_t)o * H);
    float4 c = {0.f, 0.f, 0.f, 0.f};
#pragma unroll 8
    for (int q = 0; q < H / 4; q++) {
        float4 w = wrow[q];
        float4 h = hrow[q];
        c.x = fmaf(w.x, h.x, c.x);
        c.y = fmaf(w.y, h.y, c.y);
        c.z = fmaf(w.z, h.z, c.z);
        c.w = fmaf(w.w, h.w, c.w);
    }
    float acc = bh2o[o] + (c.x + c.y) + (c.z + c.w);
    int oidx = b * O + o;                      // output (B,1,O)
    if (oidx < out_size) out[oidx] = acc;
    if (out_size >= B * O + B * H) {
#pragma unroll
        for (int q = 0; q < 2; q++) {
            int e = idx + q * (B * O);         // hidden (B,H) flat copy
            out[B * O + e] = hfin[e];
        }
    }
}

extern "C" void kernel_launch(void* const* d_in, const int* in_sizes, int n_in,
                              void* d_out, int out_size) {
    const float* seq  = (const float*)d_in[0];
    const float* Wi2h = (const float*)d_in[1];
    const float* bi2h = (const float*)d_in[2];
    const float* Wh2o = (const float*)d_in[3];
    const float* bh2o = (const float*)d_in[4];
    float* out = (float*)d_out;

    cudaFuncSetAttribute(phaseB_kernel,
                         cudaFuncAttributeMaxDynamicSharedMemorySize, SMEM_B_BYTES);

    void* pBar = nullptr;
    cudaGetSymbolAddress(&pBar, g_bar);
    cudaMemsetAsync(pBar, 0, sizeof(g_bar), 0);
    void* pH = nullptr;
    cudaGetSymbolAddress(&pH, g_H);
    cudaMemsetAsync(pH, 0, (size_t)B * H * sizeof(float), 0);  // h(0) = 0

    phaseA_kernel<<<dim3(S, H / 128), 256>>>(seq, Wi2h, bi2h);
    phaseB_kernel<<<128, 256, SMEM_B_BYTES>>>(Wi2h);
    phaseC_kernel<<<(B * O) / 256, 256>>>(Wh2o, bh2o, out, out_size);
}

// round 9
// speedup vs baseline: 1.1998x; 1.1364x over previous
#include <cuda_runtime.h>
#include <math.h>

// Elman RNN, fp32. B=128, S=1024, I=256, H=512, O=256, N_TARGETS=1.
// Phase A: P[t][b][j] = x_t @ Wx^T + bias  (fma2-packed GEMM)
// Phase B: persistent, 128 CTAs = 8 j-tiles(64j) x 16 b-groups(8b).
//          *** Wh lives in REGISTERS (128/thread) — no w LDS traffic. ***
//          h staged to smem [k][b] (linear conflict-free), 16-way k-split
//          partials in smem, reduce+tanh, publish, 8-arrival counter.
//          (R8 bug fixed: staging loop now covers all 512 k, q<4.)
// Phase C: output = h @ W_h2o^T + b_h2o ; hidden appended if requested.

typedef unsigned long long ull;

namespace {
constexpr int S = 1024, B = 128, I = 256, H = 512, O = 256;
constexpr int NJ = 8;                  // CTAs (j-tiles) per b-group
constexpr int JT = 64;                 // j per CTA
constexpr int BT = 8;                  // b per group
constexpr int PROWB = 10;              // p_s j-row stride
constexpr int PPLANE = JT * PROWB;     // 640 floats per ks plane
constexpr int H_S_FLOATS = H * BT;     // 4096 (16 KB), h_s[k][8b]
constexpr int P_S_FLOATS = 16 * PPLANE;// 10240 (40 KB)
constexpr int SMEM_B_BYTES = (H_S_FLOATS + P_S_FLOATS) * 4;  // 57344
}

__device__ float g_P[(size_t)S * B * H];   // [t][b][j] pre-activations
__device__ float g_H[2][H * B];            // ping-pong h: [parity][k][b]
__device__ struct { unsigned v; unsigned pad[31]; } g_bar[B / BT];

__device__ __forceinline__ ull pack2(float x) {
    ull r;
    asm("mov.b64 %0, {%1, %1};" : "=l"(r) : "f"(x));
    return r;
}
__device__ __forceinline__ float2 unpack2(ull v) {
    float2 r;
    asm("mov.b64 {%0, %1}, %2;" : "=f"(r.x), "=f"(r.y) : "l"(v));
    return r;
}
__device__ __forceinline__ void fma2(ull& d, ull a, ull b) {
    asm("fma.rn.f32x2 %0, %1, %2, %0;" : "+l"(d) : "l"(a), "l"(b));
}
__device__ __forceinline__ void spin_ctr(unsigned* ctr, unsigned target) {
    unsigned v;
    do {
        asm volatile("ld.acquire.gpu.u32 %0, [%1];"
                     : "=r"(v) : "l"(ctr) : "memory");
    } while (v < target);
}
__device__ __forceinline__ void arrive_ctr(unsigned* ctr) {
    asm volatile("red.release.gpu.global.add.u32 [%0], 1;" :: "l"(ctr) : "memory");
}

// ---------------- Phase A: pre-activation GEMM -> P[t][b][j] ----------------
__global__ void __launch_bounds__(256) phaseA_kernel(
    const float* __restrict__ seq, const float* __restrict__ Wi2h,
    const float* __restrict__ bi2h) {
    const int t = blockIdx.x;
    const int j0 = blockIdx.y * 128;
    const int tid = threadIdx.x;
    const int tx = tid & 15;   // j-block: 8 j per thread
    const int ty = tid >> 4;   // b-block: 8 b per thread (4 fma2 pairs)
    __shared__ float sh_w[16 * 132];  // [k][j], padded
    __shared__ float sh_x[16 * 132];  // [k][b], padded
    ull acc[4][8];                    // [b-pair][j]
#pragma unroll
    for (int r = 0; r < 4; r++)
#pragma unroll
        for (int c = 0; c < 8; c++) acc[r][c] = 0;

    for (int k0 = 0; k0 < I; k0 += 16) {
        __syncthreads();
#pragma unroll
        for (int q = 0; q < 2; q++) {
            int idx = tid + q * 256;  // 0..511
            int j = idx >> 2, kq = idx & 3;
            float4 v = *(const float4*)(Wi2h + (size_t)(j0 + j) * (I + H) + k0 + kq * 4);
            sh_w[(kq * 4 + 0) * 132 + j] = v.x;
            sh_w[(kq * 4 + 1) * 132 + j] = v.y;
            sh_w[(kq * 4 + 2) * 132 + j] = v.z;
            sh_w[(kq * 4 + 3) * 132 + j] = v.w;
        }
#pragma unroll
        for (int q = 0; q < 2; q++) {
            int idx = tid + q * 256;
            int b = idx >> 2, kq = idx & 3;
            float4 v = *(const float4*)(seq + (size_t)b * (S * I) + (size_t)t * I + k0 + kq * 4);
            sh_x[(kq * 4 + 0) * 132 + b] = v.x;
            sh_x[(kq * 4 + 1) * 132 + b] = v.y;
            sh_x[(kq * 4 + 2) * 132 + b] = v.z;
            sh_x[(kq * 4 + 3) * 132 + b] = v.w;
        }
        __syncthreads();
#pragma unroll
        for (int k = 0; k < 16; k++) {
            ulonglong2 x01 = *(const ulonglong2*)(sh_x + k * 132 + ty * 8);
            ulonglong2 x23 = *(const ulonglong2*)(sh_x + k * 132 + ty * 8 + 4);
            float4 w0 = *(const float4*)(sh_w + k * 132 + tx * 8);
            float4 w1 = *(const float4*)(sh_w + k * 132 + tx * 8 + 4);
            ull ww[8] = {pack2(w0.x), pack2(w0.y), pack2(w0.z), pack2(w0.w),
                         pack2(w1.x), pack2(w1.y), pack2(w1.z), pack2(w1.w)};
#pragma unroll
            for (int c = 0; c < 8; c++) {
                fma2(acc[0][c], x01.x, ww[c]);
                fma2(acc[1][c], x01.y, ww[c]);
                fma2(acc[2][c], x23.x, ww[c]);
                fma2(acc[3][c], x23.y, ww[c]);
            }
        }
    }
    float4 bj0 = *(const float4*)(bi2h + j0 + tx * 8);
    float4 bj1 = *(const float4*)(bi2h + j0 + tx * 8 + 4);
    float bj[8] = {bj0.x, bj0.y, bj0.z, bj0.w, bj1.x, bj1.y, bj1.z, bj1.w};
#pragma unroll
    for (int r = 0; r < 4; r++) {
        float lo[8], hi[8];
#pragma unroll
        for (int c = 0; c < 8; c++) {
            float2 f = unpack2(acc[r][c]);
            lo[c] = f.x + bj[c];
            hi[c] = f.y + bj[c];
        }
        int b_even = ty * 8 + 2 * r;
        float* op0 = g_P + (size_t)t * (B * H) + (size_t)b_even * H + j0 + tx * 8;
        float* op1 = op0 + H;
        *(float4*)op0 = make_float4(lo[0], lo[1], lo[2], lo[3]);
        *(float4*)(op0 + 4) = make_float4(lo[4], lo[5], lo[6], lo[7]);
        *(float4*)op1 = make_float4(hi[0], hi[1], hi[2], hi[3]);
        *(float4*)(op1 + 4) = make_float4(hi[4], hi[5], hi[6], hi[7]);
    }
}

// ---------------- Phase B: Wh-in-registers persistent recurrence ------------
__global__ void __launch_bounds__(256, 1) phaseB_kernel(const float* __restrict__ Wi2h) {
    extern __shared__ float smem[];
    float* h_s = smem;                 // [512 k][8 b]  (linear, no pad)
    float* p_s = smem + H_S_FLOATS;    // [16 ks][64 j (stride 10)]

    const int g = blockIdx.x & 15;     // b-group
    const int jj = blockIdx.x >> 4;    // j-tile
    const int j0 = jj * JT;
    const int tid = threadIdx.x;
    const int warp = tid >> 5;
    const int lane = tid & 31;
    const int kp = lane >> 4;          // k parity within chunk
    const int jq = lane & 15;          // j quad: j = jq*4..+3
    const int kbase = warp * 64 + kp;

    // ---- load Wh into registers: lane owns 32 k x 4 j = 128 floats ----
    float wreg[128];
#pragma unroll
    for (int i = 0; i < 32; i++) {
        int k = kbase + 2 * i;
#pragma unroll
        for (int j = 0; j < 4; j++)
            wreg[i * 4 + j] =
                Wi2h[(size_t)(j0 + jq * 4 + j) * (I + H) + I + k];
    }

    unsigned* ctr = &g_bar[g].v;
    const int rj = tid & 63;           // reducer: local j
    const int rb = (tid >> 6) * 2;     // reducer: b pair base (0,2,4,6)

    for (int t = 0; t < S; t++) {
        // wait for all peers' h(t) publishes
        if (tid == 0) spin_ctr(ctr, (unsigned)t * NJ);
        __syncthreads();

        const float* rbuf = g_H[t & 1];          // [k][128 b]
        float* wbuf = g_H[(t + 1) & 1];

        // P prefetch (consumed at reduce)
        const float* pPt = g_P + (size_t)t * (B * H) + (size_t)(g * BT) * H;
        float pv0 = pPt[(rb + 0) * H + j0 + rj];
        float pv1 = pPt[(rb + 1) * H + j0 + rj];

        // stage full h slice: h_s[k][0..7] <- rbuf[k][g*8..g*8+7], k=0..511
        // 1024 float4 slots -> 4 rounds of 256 threads (linear, conflict-free)
#pragma unroll
        for (int q = 0; q < 4; q++) {
            int idx = tid + q * 256;             // 0..1023
            int k = idx >> 1, half = idx & 1;
            float4 v = *(const float4*)(rbuf + (size_t)k * B + g * BT + half * 4);
            *(float4*)(h_s + idx * 4) = v;
        }
        __syncthreads();

        // ---- compute: fma2 over b-pairs, w from registers ----
        ull acc[4][4];                           // [j][b-pair]
#pragma unroll
        for (int j = 0; j < 4; j++)
#pragma unroll
            for (int p = 0; p < 4; p++) acc[j][p] = 0;
#pragma unroll
        for (int i = 0; i < 32; i++) {
            const float* hr = h_s + (kbase + 2 * i) * BT;
            ulonglong2 hA = *(const ulonglong2*)hr;        // b0..b3
            ulonglong2 hB = *(const ulonglong2*)(hr + 4);  // b4..b7
#pragma unroll
            for (int j = 0; j < 4; j++) {
                ull wv = pack2(wreg[i * 4 + j]);
                fma2(acc[j][0], wv, hA.x);
                fma2(acc[j][1], wv, hA.y);
                fma2(acc[j][2], wv, hB.x);
                fma2(acc[j][3], wv, hB.y);
            }
        }

        // store k-split partials: p_s[ks][j][b] (PROWB=10 -> bank-exact)
        {
            float* pst = p_s + (warp * 2 + kp) * PPLANE + (jq * 4) * PROWB;
#pragma unroll
            for (int j = 0; j < 4; j++)
#pragma unroll
                for (int p = 0; p < 4; p++)
                    *(ull*)(pst + j * PROWB + p * 2) = acc[j][p];
        }
        __syncthreads();

        // reduce 16 partials + P, tanh, publish to g_H[(t+1)&1][k][b]
        {
            float s0 = pv0, s1 = pv1;
            const float* prd = p_s + rj * PROWB + rb;
#pragma unroll
            for (int z = 0; z < 16; z++) {
                s0 += prd[z * PPLANE];
                s1 += prd[z * PPLANE + 1];
            }
            float2 hv = {tanhf(s0), tanhf(s1)};
            *(float2*)(wbuf + (size_t)(j0 + rj) * B + g * BT + rb) = hv;
        }
        __syncthreads();
        if (tid == 0) arrive_ctr(ctr);
    }
}

// ---------------- Phase C: output projection + hidden emit ----------------
__global__ void __launch_bounds__(256) phaseC_kernel(
    const float* __restrict__ Wh2o, const float* __restrict__ bh2o,
    float* __restrict__ out, int out_size) {
    const float* hfin = g_H[S & 1];            // [k][b], written at final step
    int idx = blockIdx.x * 256 + threadIdx.x;  // 0..32767
    int o = idx >> 7, b = idx & 127;
    float acc = bh2o[o];
    const float* wrow = Wh2o + (size_t)o * H;
#pragma unroll 8
    for (int k = 0; k < H; k++)
        acc = fmaf(hfin[(size_t)k * B + b], __ldg(wrow + k), acc);
    int oidx = b * O + o;                      // output (B,1,O)
    if (oidx < out_size) out[oidx] = acc;
    if (out_size >= B * O + B * H) {
#pragma unroll
        for (int q = 0; q < 2; q++) {
            int e = idx + q * (B * O);         // hidden (B,H): e = b*512+k
            int hb = e >> 9, hk = e & 511;
            out[B * O + e] = hfin[(size_t)hk * B + hb];
        }
    }
}

extern "C" void kernel_launch(void* const* d_in, const int* in_sizes, int n_in,
                              void* d_out, int out_size) {
    const float* seq  = (const float*)d_in[0];
    const float* Wi2h = (const float*)d_in[1];
    const float* bi2h = (const float*)d_in[2];
    const float* Wh2o = (const float*)d_in[3];
    const float* bh2o = (const float*)d_in[4];
    float* out = (float*)d_out;

    cudaFuncSetAttribute(phaseB_kernel,
                         cudaFuncAttributeMaxDynamicSharedMemorySize, SMEM_B_BYTES);

    void* pBar = nullptr;
    cudaGetSymbolAddress(&pBar, g_bar);
    cudaMemsetAsync(pBar, 0, sizeof(g_bar), 0);
    void* pH = nullptr;
    cudaGetSymbolAddress(&pH, g_H);
    cudaMemsetAsync(pH, 0, (size_t)H * B * sizeof(float), 0);  // h(0) = 0

    phaseA_kernel<<<dim3(S, H / 128), 256>>>(seq, Wi2h, bi2h);
    phaseB_kernel<<<128, 256, SMEM_B_BYTES>>>(Wi2h);
    phaseC_kernel<<<(B * O) / 256, 256>>>(Wh2o, bh2o, out, out_size);
}